// round 14
// baseline (speedup 1.0000x reference)
#include <cuda_runtime.h>
#include <cuda_bf16.h>
#include <math.h>
#include <stdint.h>

#define B_  2
#define L_  768
#define E_  768
#define H_  12
#define DH_ 64
#define D_  8
#define DS_ 8
#define INV_SQRT_DS 0.35355339059327373f
#define ALPHA_ 2.5f

// ---------------- scratch (static device globals; no allocation) -------------
__device__ float  g_Q[B_*H_*L_*DH_];
__device__ float  g_K[B_*H_*L_*DH_];
__device__ float  g_V[B_*H_*L_*DH_];
__device__ float  g_S[B_*H_*D_*L_];      // per (b,h,d,q): softmax denom (m=0)
__device__ double g_acc[B_*D_*4];        // sums over (h,q): var, max, hhi, ent

__device__ __forceinline__ uint32_t smem_u32(const void* p) {
    uint32_t a;
    asm("{ .reg .u64 t; cvta.to.shared.u64 t, %1; cvt.u32.u64 %0, t; }"
        : "=r"(a) : "l"(p));
    return a;
}

// packed f32x2 helpers (dual-lane fp32 FMA on one issue slot)
#define FMA2(d, a, b, c) \
    asm("fma.rn.f32x2 %0, %1, %2, %3;" : "=l"(d) : "l"(a), "l"(b), "l"(c))
#define PACK2(d, lo, hi) \
    asm("mov.b64 %0, {%1, %2};" : "=l"(d) : "f"(lo), "f"(hi))
#define UNPACK2(lo, hi, s) \
    asm("mov.b64 {%0, %1}, %2;" : "=f"(lo), "=f"(hi) : "l"(s))

// ============================================================================
// K1: fused split + mma.sync bf16 projection GEMM (round-11, unchanged).
// ============================================================================
#define PSA 40
#define PSB 72
#define PBUF (128*PSA + 128*PSA + 32*PSB + 32*PSB)
#define PROJ_SMEM (2 * PBUF * 2)

__device__ __forceinline__ void cvt_split4(float4 v, ushort4& h, ushort4& l) {
    float f[4] = {v.x, v.y, v.z, v.w};
    unsigned short* ph = &h.x;
    unsigned short* pl = &l.x;
    #pragma unroll
    for (int i = 0; i < 4; i++) {
        __nv_bfloat16 hi = __float2bfloat16(f[i]);
        ph[i] = __bfloat16_as_ushort(hi);
        pl[i] = __bfloat16_as_ushort(__float2bfloat16(f[i] - __bfloat162float(hi)));
    }
}

__global__ __launch_bounds__(256) void proj_mma_kernel(
    const float* __restrict__ X,
    const float* __restrict__ Wq, const float* __restrict__ bq,
    const float* __restrict__ Wk, const float* __restrict__ bk,
    const float* __restrict__ Wv, const float* __restrict__ bv)
{
    extern __shared__ __align__(16) __nv_bfloat16 smp[];

    const int t = threadIdx.x, warp = t >> 5, lane = t & 31;
    const int wm = warp & 3, wn = warp >> 2;
    const int z = blockIdx.z;
    const int row0 = blockIdx.y * 128, col0 = blockIdx.x * 64;

    if (blockIdx.x == 0 && blockIdx.y == 0 && z == 0 && t < B_*D_*4)
        g_acc[t] = 0.0;

    const float* W   = (z == 0) ? Wq : (z == 1) ? Wk : Wv;
    const float* bias = (z == 0) ? bq : (z == 1) ? bk : bv;
    float* out = (z == 0) ? g_Q : (z == 1) ? g_K : g_V;

    int ar[4], ak[4], br[2], bn[2];
    #pragma unroll
    for (int j = 0; j < 4; j++) { int c = t + j * 256; ar[j] = c >> 3; ak[j] = (c & 7) * 4; }
    #pragma unroll
    for (int j = 0; j < 2; j++) { int c = t + j * 256; br[j] = c >> 4; bn[j] = (c & 15) * 4; }

    float4 raf[4], rbf[2];
    auto ld_regs = [&](int kk) {
        #pragma unroll
        for (int j = 0; j < 4; j++)
            raf[j] = *reinterpret_cast<const float4*>(&X[(size_t)(row0 + ar[j]) * E_ + kk + ak[j]]);
        #pragma unroll
        for (int j = 0; j < 2; j++)
            rbf[j] = *reinterpret_cast<const float4*>(&W[(size_t)(kk + br[j]) * E_ + col0 + bn[j]]);
    };
    auto st_smem = [&](int buf) {
        __nv_bfloat16* Ah = smp + buf * PBUF;
        __nv_bfloat16* Al = Ah + 128 * PSA;
        __nv_bfloat16* Bh = Al + 128 * PSA;
        __nv_bfloat16* Bl = Bh + 32 * PSB;
        #pragma unroll
        for (int j = 0; j < 4; j++) {
            ushort4 h, l;
            cvt_split4(raf[j], h, l);
            *reinterpret_cast<ushort4*>(&Ah[ar[j] * PSA + ak[j]]) = h;
            *reinterpret_cast<ushort4*>(&Al[ar[j] * PSA + ak[j]]) = l;
        }
        #pragma unroll
        for (int j = 0; j < 2; j++) {
            ushort4 h, l;
            cvt_split4(rbf[j], h, l);
            *reinterpret_cast<ushort4*>(&Bh[br[j] * PSB + bn[j]]) = h;
            *reinterpret_cast<ushort4*>(&Bl[br[j] * PSB + bn[j]]) = l;
        }
    };

    float acc[2][4][4];
    #pragma unroll
    for (int mt = 0; mt < 2; mt++)
        #pragma unroll
        for (int nt = 0; nt < 4; nt++)
            #pragma unroll
            for (int i = 0; i < 4; i++) acc[mt][nt][i] = 0.f;

    ld_regs(0);
    st_smem(0);
    __syncthreads();

    int buf = 0;
    for (int it = 0; it < 24; it++) {
        if (it + 1 < 24) ld_regs((it + 1) * 32);

        const __nv_bfloat16* Ah = smp + buf * PBUF;
        const __nv_bfloat16* Al = Ah + 128 * PSA;
        const __nv_bfloat16* Bh = Al + 128 * PSA;
        const __nv_bfloat16* Bl = Bh + 32 * PSB;

        #pragma unroll
        for (int ks = 0; ks < 2; ks++) {
            uint32_t ah[2][4], al[2][4];
            #pragma unroll
            for (int mt = 0; mt < 2; mt++) {
                int arow = wm * 32 + mt * 16 + (lane & 15);
                int acol = ks * 16 + (lane >> 4) * 8;
                uint32_t ad = smem_u32(&Ah[arow * PSA + acol]);
                asm volatile("ldmatrix.sync.aligned.m8n8.x4.shared.b16 {%0,%1,%2,%3}, [%4];"
                    : "=r"(ah[mt][0]), "=r"(ah[mt][1]), "=r"(ah[mt][2]), "=r"(ah[mt][3])
                    : "r"(ad));
                uint32_t ad2 = smem_u32(&Al[arow * PSA + acol]);
                asm volatile("ldmatrix.sync.aligned.m8n8.x4.shared.b16 {%0,%1,%2,%3}, [%4];"
                    : "=r"(al[mt][0]), "=r"(al[mt][1]), "=r"(al[mt][2]), "=r"(al[mt][3])
                    : "r"(ad2));
            }
            #pragma unroll
            for (int nt = 0; nt < 4; nt++) {
                int brow = ks * 16 + (lane & 15);
                int bcol = wn * 32 + nt * 8;
                uint32_t bh0, bh1, bl0, bl1;
                uint32_t bd = smem_u32(&Bh[brow * PSB + bcol]);
                asm volatile("ldmatrix.sync.aligned.m8n8.x2.trans.shared.b16 {%0,%1}, [%2];"
                    : "=r"(bh0), "=r"(bh1) : "r"(bd));
                uint32_t bd2 = smem_u32(&Bl[brow * PSB + bcol]);
                asm volatile("ldmatrix.sync.aligned.m8n8.x2.trans.shared.b16 {%0,%1}, [%2];"
                    : "=r"(bl0), "=r"(bl1) : "r"(bd2));
                #pragma unroll
                for (int mt = 0; mt < 2; mt++) {
                    asm volatile(
                        "mma.sync.aligned.m16n8k16.row.col.f32.bf16.bf16.f32 "
                        "{%0,%1,%2,%3}, {%4,%5,%6,%7}, {%8,%9}, {%0,%1,%2,%3};"
                        : "+f"(acc[mt][nt][0]), "+f"(acc[mt][nt][1]),
                          "+f"(acc[mt][nt][2]), "+f"(acc[mt][nt][3])
                        : "r"(ah[mt][0]), "r"(ah[mt][1]), "r"(ah[mt][2]), "r"(ah[mt][3]),
                          "r"(bh0), "r"(bh1));
                    asm volatile(
                        "mma.sync.aligned.m16n8k16.row.col.f32.bf16.bf16.f32 "
                        "{%0,%1,%2,%3}, {%4,%5,%6,%7}, {%8,%9}, {%0,%1,%2,%3};"
                        : "+f"(acc[mt][nt][0]), "+f"(acc[mt][nt][1]),
                          "+f"(acc[mt][nt][2]), "+f"(acc[mt][nt][3])
                        : "r"(ah[mt][0]), "r"(ah[mt][1]), "r"(ah[mt][2]), "r"(ah[mt][3]),
                          "r"(bl0), "r"(bl1));
                    asm volatile(
                        "mma.sync.aligned.m16n8k16.row.col.f32.bf16.bf16.f32 "
                        "{%0,%1,%2,%3}, {%4,%5,%6,%7}, {%8,%9}, {%0,%1,%2,%3};"
                        : "+f"(acc[mt][nt][0]), "+f"(acc[mt][nt][1]),
                          "+f"(acc[mt][nt][2]), "+f"(acc[mt][nt][3])
                        : "r"(al[mt][0]), "r"(al[mt][1]), "r"(al[mt][2]), "r"(al[mt][3]),
                          "r"(bh0), "r"(bh1));
                }
            }
        }
        __syncthreads();
        if (it + 1 < 24) {
            st_smem(buf ^ 1);
            __syncthreads();
            buf ^= 1;
        }
    }

    #pragma unroll
    for (int mt = 0; mt < 2; mt++) {
        #pragma unroll
        for (int nt = 0; nt < 4; nt++) {
            int r = row0 + wm * 32 + mt * 16 + (lane >> 2);
            int c = col0 + wn * 32 + nt * 8 + (lane & 3) * 2;
            int h = c >> 6, dh = c & 63;
            float bz0 = bias[c], bz1 = bias[c + 1];
            #pragma unroll
            for (int half = 0; half < 2; half++) {
                int rr = r + half * 8;
                int b = rr / L_, l = rr % L_;
                float* op = &out[(size_t)((b * H_ + h) * L_ + l) * DH_ + dh];
                float2 v;
                v.x = acc[mt][nt][half * 2 + 0] + bz0;
                v.y = acc[mt][nt][half * 2 + 1] + bz1;
                *reinterpret_cast<float2*>(op) = v;
            }
        }
    }
}

// ============================================================================
// K2 (v3): branchless stats, m=0; f32x2 dots; 128 q rows per block
// (grid 192 x 6 = 1152 blocks; 4x less K staging).  Q rows are read from
// smem inside the k-loop (warp-broadcast LDS) -> low register pressure.
// Warp handles 16 rows; stats arrays S/E1/E2/M[16] in regs.
// ============================================================================
#define SQROWS 128

__global__ __launch_bounds__(256) void stats_kernel(const float* __restrict__ mask)
{
    __shared__ float sk[L_ * 12];
    __shared__ float sq[SQROWS * 8];
    __shared__ float smask[L_];
    __shared__ float sred[8][4];

    const int t = threadIdx.x;
    const int bhd = blockIdx.x;
    const int d = bhd & 7;
    const int h = (bhd >> 3) % H_;
    const int b = bhd / (8 * H_);
    const int q0 = blockIdx.y * SQROWS;

    const float* Kbase = &g_K[(size_t)(b * H_ + h) * L_ * DH_ + d * 8];

    for (int i = t; i < L_ * 2; i += 256) {
        int k = i >> 1, half = (i & 1) * 4;
        *reinterpret_cast<float4*>(&sk[k * 12 + half]) =
            *reinterpret_cast<const float4*>(&Kbase[(size_t)k * DH_ + half]);
    }
    for (int i = t; i < SQROWS * 8; i += 256)
        sq[i] = g_Q[(size_t)((b * H_ + h) * L_ + q0 + (i >> 3)) * DH_ + d * 8 + (i & 7)];
    for (int i = t; i < L_; i += 256) smask[i] = mask[b * L_ + i];
    __syncthreads();

    const int warp = t >> 5, lane = t & 31;
    const int r0 = warp * 16;

    const unsigned long long z2 = 0ull;
    float S[16], E1[16], E2[16], M[16];
    #pragma unroll
    for (int r = 0; r < 16; r++) { S[r] = 0.f; E1[r] = 0.f; E2[r] = 0.f; M[r] = -1e30f; }

    for (int kb = 0; kb < L_; kb += 32) {
        int k = kb + lane;
        ulonglong2 ka = *reinterpret_cast<const ulonglong2*>(&sk[k * 12]);
        ulonglong2 kb2 = *reinterpret_cast<const ulonglong2*>(&sk[k * 12 + 4]);
        unsigned long long k2[4] = {ka.x, ka.y, kb2.x, kb2.y};
        float mk = smask[k];
        #pragma unroll
        for (int r = 0; r < 16; r++) {
            // q row read from smem: same address across lanes -> broadcast
            ulonglong2 qa = *reinterpret_cast<const ulonglong2*>(&sq[(r0 + r) * 8]);
            ulonglong2 qb = *reinterpret_cast<const ulonglong2*>(&sq[(r0 + r) * 8 + 4]);
            unsigned long long s2;
            FMA2(s2, qa.x, k2[0], z2);
            FMA2(s2, qa.y, k2[1], s2);
            FMA2(s2, qb.x, k2[2], s2);
            FMA2(s2, qb.y, k2[3], s2);
            float lo, hi;
            UNPACK2(lo, hi, s2);
            float s = fmaf(lo + hi, INV_SQRT_DS, mk);
            float e = __expf(s);
            S[r]  += e;
            E1[r]  = fmaf(e, s, E1[r]);
            E2[r]  = fmaf(e, e, E2[r]);
            M[r]   = fmaxf(M[r], s);
        }
    }

    #pragma unroll
    for (int r = 0; r < 16; r++) {
        #pragma unroll
        for (int off = 16; off > 0; off >>= 1) {
            S[r]  += __shfl_xor_sync(0xffffffff, S[r],  off);
            E1[r] += __shfl_xor_sync(0xffffffff, E1[r], off);
            E2[r] += __shfl_xor_sync(0xffffffff, E2[r], off);
            M[r]   = fmaxf(M[r], __shfl_xor_sync(0xffffffff, M[r], off));
        }
    }

    if (lane == 0) {
        float psum[4] = {0.f, 0.f, 0.f, 0.f};
        #pragma unroll
        for (int r = 0; r < 16; r++) {
            int row  = q0 + r0 + r;
            int ridx = ((b * H_ + h) * D_ + d) * L_ + row;
            g_S[ridx] = S[r];
            float inv  = 1.0f / S[r];
            float maxp = __expf(M[r]) * inv;
            float hhi  = E2[r] * inv * inv;
            float var  = (hhi - (1.0f / (float)L_)) * (1.0f / (float)(L_ - 1));
            float ent  = __logf(S[r]) - E1[r] * inv;
            psum[0] += var; psum[1] += maxp; psum[2] += hhi; psum[3] += ent;
        }
        #pragma unroll
        for (int i = 0; i < 4; i++) sred[warp][i] = psum[i];
    }
    __syncthreads();
    if (t == 0) {
        double tot[4] = {0, 0, 0, 0};
        #pragma unroll
        for (int w = 0; w < 8; w++)
            #pragma unroll
            for (int i = 0; i < 4; i++) tot[i] += (double)sred[w][i];
        #pragma unroll
        for (int i = 0; i < 4; i++)
            atomicAdd(&g_acc[(b * D_ + d) * 4 + i], tot[i]);
    }
}

// ============================================================================
// K4: attn — weights in prologue; 4q x 4k score tile; m=0; f32x2; float4 sA.
// (round-13 form, unchanged)
// ============================================================================
#define QT 32
#define KT 128
#define KPAD 68
#define APAD 132

__global__ __launch_bounds__(256, 2) void attn_kernel(
    const float* __restrict__ mask,
    float* __restrict__ out_ctx,
    float* __restrict__ out_attn)
{
    extern __shared__ float smem_[];
    float* sQ   = smem_;
    float* sMul = sQ   + QT * DH_;
    float* sW   = sMul + QT * D_;        // 8 gate weights for this b
    float* sK   = sW   + D_;
    float* sV   = sK   + KT * KPAD;
    float* smk  = sV   + KT * KPAD;
    float* sA   = sK;

    const int t    = threadIdx.x;
    const int bh   = blockIdx.x;
    const int b    = bh / H_;
    const int q0   = blockIdx.y * QT;
    const int w    = t >> 5;
    const int lane = t & 31;
    const int kspl = lane >> 3;
    const int dhc  = lane & 7;

    const float* Qbase = &g_Q[(size_t)(bh * L_ + q0) * DH_];
    const float* Kbase = &g_K[(size_t)bh * L_ * DH_];
    const float* Vbase = &g_V[(size_t)bh * L_ * DH_];

    for (int i = t; i < QT * DH_ / 4; i += 256)
        *reinterpret_cast<float4*>(&sQ[i * 4]) =
            *reinterpret_cast<const float4*>(&Qbase[i * 4]);

    // gate weights (stats kernel boundary guarantees g_acc is final)
    if (t < 8) {
        const float scale = 1.0f / (float)(H_ * L_);
        float st[4];
        #pragma unroll
        for (int i = 0; i < 4; i++)
            st[i] = (float)(g_acc[(b * D_ + t) * 4 + i]) * scale;
        float n[4];
        #pragma unroll
        for (int i = 0; i < 4; i++) {
            float vmin = st[i], vmax = st[i];
            #pragma unroll
            for (int off = 1; off < 8; off <<= 1) {
                vmin = fminf(vmin, __shfl_xor_sync(0xff, vmin, off));
                vmax = fmaxf(vmax, __shfl_xor_sync(0xff, vmax, off));
            }
            n[i] = (st[i] - vmin) / fmaxf(vmax - vmin, 1e-12f);
        }
        float score = 0.5f * n[0] + 0.3f * n[1] + 0.2f * n[2] - 0.4f * n[3];
        float smax = score;
        #pragma unroll
        for (int off = 1; off < 8; off <<= 1)
            smax = fmaxf(smax, __shfl_xor_sync(0xff, smax, off));
        float e = __expf(ALPHA_ * (score - smax));
        float ssum = e;
        #pragma unroll
        for (int off = 1; off < 8; off <<= 1)
            ssum += __shfl_xor_sync(0xff, ssum, off);
        sW[t] = e / ssum;
    }
    __syncthreads();
    {
        int q = t >> 3, dd = t & 7;
        int ridx = (bh * D_ + dd) * L_ + q0 + q;
        sMul[q * 8 + dd] = sW[dd] / g_S[ridx];
    }

    const unsigned long long z2 = 0ull;
    unsigned long long ctx2[4][4];
    #pragma unroll
    for (int qi = 0; qi < 4; qi++)
        #pragma unroll
        for (int j = 0; j < 4; j++) ctx2[qi][j] = 0ull;

    for (int kt = 0; kt < L_; kt += KT) {
        __syncthreads();
        for (int i = t; i < KT * DH_ / 4; i += 256) {
            int k = i >> 4, c = (i & 15) * 4;
            *reinterpret_cast<float4*>(&sK[k * KPAD + c]) =
                *reinterpret_cast<const float4*>(&Kbase[(size_t)(kt + k) * DH_ + c]);
            *reinterpret_cast<float4*>(&sV[k * KPAD + c]) =
                *reinterpret_cast<const float4*>(&Vbase[(size_t)(kt + k) * DH_ + c]);
        }
        if (t < KT) smk[t] = mask[b * L_ + kt + t];
        __syncthreads();

        float acc[4][4];
        #pragma unroll
        for (int qi = 0; qi < 4; qi++)
            #pragma unroll
            for (int kj = 0; kj < 4; kj++) acc[qi][kj] = 0.f;

        float mk[4];
        #pragma unroll
        for (int kj = 0; kj < 4; kj++) mk[kj] = smk[lane + 32 * kj];

        #pragma unroll
        for (int dd = 0; dd < D_; dd++) {
            unsigned long long q2[4][4];
            float mu[4];
            #pragma unroll
            for (int qi = 0; qi < 4; qi++) {
                const float* qp = &sQ[(4 * w + qi) * DH_ + dd * 8];
                ulonglong2 qa = *reinterpret_cast<const ulonglong2*>(qp);
                ulonglong2 qb = *reinterpret_cast<const ulonglong2*>(qp + 4);
                q2[qi][0] = qa.x; q2[qi][1] = qa.y;
                q2[qi][2] = qb.x; q2[qi][3] = qb.y;
                mu[qi] = sMul[(4 * w + qi) * 8 + dd];
            }
            #pragma unroll
            for (int kj = 0; kj < 4; kj++) {
                const float* kp = &sK[(lane + 32 * kj) * KPAD + dd * 8];
                ulonglong2 ka = *reinterpret_cast<const ulonglong2*>(kp);
                ulonglong2 kb2 = *reinterpret_cast<const ulonglong2*>(kp + 4);
                unsigned long long k2[4] = {ka.x, ka.y, kb2.x, kb2.y};
                #pragma unroll
                for (int qi = 0; qi < 4; qi++) {
                    unsigned long long s2;
                    FMA2(s2, q2[qi][0], k2[0], z2);
                    FMA2(s2, q2[qi][1], k2[1], s2);
                    FMA2(s2, q2[qi][2], k2[2], s2);
                    FMA2(s2, q2[qi][3], k2[3], s2);
                    float lo, hi;
                    UNPACK2(lo, hi, s2);
                    float s = fmaf(lo + hi, INV_SQRT_DS, mk[kj]);
                    acc[qi][kj] = fmaf(mu[qi], __expf(s), acc[qi][kj]);
                }
            }
        }

        #pragma unroll
        for (int qi = 0; qi < 4; qi++) {
            float* row = &out_attn[(size_t)(bh * L_ + q0 + 4 * w + qi) * L_ + kt];
            #pragma unroll
            for (int kj = 0; kj < 4; kj++)
                row[lane + 32 * kj] = acc[qi][kj];
        }

        __syncthreads();
        #pragma unroll
        for (int qi = 0; qi < 4; qi++)
            #pragma unroll
            for (int kj = 0; kj < 4; kj++)
                sA[(4 * w + qi) * APAD + lane + 32 * kj] = acc[qi][kj];
        __syncthreads();

        // ctx phase: float4 sA loads (groups of 4 consecutive k)
        #pragma unroll
        for (int j = 0; j < 4; j++) {
            const int kbase = 32 * j + 8 * kspl;
            #pragma unroll
            for (int rg = 0; rg < 2; rg++) {
                float4 a4[4];
                #pragma unroll
                for (int qi = 0; qi < 4; qi++)
                    a4[qi] = *reinterpret_cast<const float4*>(
                        &sA[(4 * w + qi) * APAD + kbase + rg * 4]);
                #pragma unroll
                for (int u = 0; u < 4; u++) {
                    int k = kbase + rg * 4 + u;
                    const float* vp = &sV[k * KPAD + dhc * 4];
                    ulonglong2 v01 = *reinterpret_cast<const ulonglong2*>(vp);
                    ulonglong2 v23 = *reinterpret_cast<const ulonglong2*>(vp + 32);
                    #pragma unroll
                    for (int qi = 0; qi < 4; qi++) {
                        float av = (&a4[qi].x)[u];
                        unsigned long long av2;
                        PACK2(av2, av, av);
                        FMA2(ctx2[qi][0], av2, v01.x, ctx2[qi][0]);
                        FMA2(ctx2[qi][1], av2, v01.y, ctx2[qi][1]);
                        FMA2(ctx2[qi][2], av2, v23.x, ctx2[qi][2]);
                        FMA2(ctx2[qi][3], av2, v23.y, ctx2[qi][3]);
                    }
                }
            }
        }
    }

    float ctx[4][8];
    #pragma unroll
    for (int qi = 0; qi < 4; qi++)
        #pragma unroll
        for (int j = 0; j < 4; j++)
            UNPACK2(ctx[qi][j * 2], ctx[qi][j * 2 + 1], ctx2[qi][j]);

    #pragma unroll
    for (int qi = 0; qi < 4; qi++)
        #pragma unroll
        for (int j = 0; j < 8; j++) {
            ctx[qi][j] += __shfl_xor_sync(0xffffffff, ctx[qi][j], 8);
            ctx[qi][j] += __shfl_xor_sync(0xffffffff, ctx[qi][j], 16);
        }

    {
        int qg = q0 + 4 * w + kspl;
        float* op = &out_ctx[(size_t)(b * L_ + qg) * E_ + (bh % H_) * DH_ + dhc * 4];
        *reinterpret_cast<float4*>(op) =
            make_float4(ctx[kspl][0], ctx[kspl][1], ctx[kspl][2], ctx[kspl][3]);
        *reinterpret_cast<float4*>(op + 32) =
            make_float4(ctx[kspl][4], ctx[kspl][5], ctx[kspl][6], ctx[kspl][7]);
    }
}

// ============================================================================
extern "C" void kernel_launch(void* const* d_in, const int* in_sizes, int n_in,
                              void* d_out, int out_size)
{
    const float* hs   = (const float*)d_in[0];
    const float* mask = (const float*)d_in[1];
    const float* Wq   = (const float*)d_in[2];
    const float* bq   = (const float*)d_in[3];
    const float* Wk   = (const float*)d_in[4];
    const float* bk   = (const float*)d_in[5];
    const float* Wv   = (const float*)d_in[6];
    const float* bv   = (const float*)d_in[7];

    float* out_ctx  = (float*)d_out;
    float* out_attn = out_ctx + (size_t)B_ * L_ * E_;

    cudaFuncSetAttribute(proj_mma_kernel,
                         cudaFuncAttributeMaxDynamicSharedMemorySize, PROJ_SMEM);
    proj_mma_kernel<<<dim3(E_ / 64, (B_ * L_) / 128, 3), 256, PROJ_SMEM>>>(
        hs, Wq, bq, Wk, bk, Wv, bv);

    stats_kernel<<<dim3(B_ * H_ * D_, L_ / SQROWS), 256>>>(mask);

    const int smem_bytes = (QT * DH_ + QT * D_ + D_ + 2 * KT * KPAD + KT) * (int)sizeof(float);
    cudaFuncSetAttribute(attn_kernel, cudaFuncAttributeMaxDynamicSharedMemorySize, smem_bytes);
    attn_kernel<<<dim3(B_ * H_, L_ / QT), 256, smem_bytes>>>(mask, out_ctx, out_attn);
}

// round 15
// speedup vs baseline: 1.0937x; 1.0937x over previous
#include <cuda_runtime.h>
#include <cuda_bf16.h>
#include <math.h>
#include <stdint.h>

#define B_  2
#define L_  768
#define E_  768
#define H_  12
#define DH_ 64
#define D_  8
#define DS_ 8
#define INV_SQRT_DS 0.35355339059327373f
#define ALPHA_ 2.5f

// ---------------- scratch (static device globals; no allocation) -------------
__device__ float  g_Q[B_*H_*L_*DH_];
__device__ float  g_K[B_*H_*L_*DH_];
__device__ float  g_Kt[B_*H_*D_*L_*8];   // depth-major K copy for stats staging
__device__ float  g_V[B_*H_*L_*DH_];
__device__ float  g_S[B_*H_*D_*L_];      // per (b,h,d,q): softmax denom (m=0)
__device__ double g_acc[B_*D_*4];        // sums over (h,q): var, max, hhi, ent

__device__ __forceinline__ uint32_t smem_u32(const void* p) {
    uint32_t a;
    asm("{ .reg .u64 t; cvta.to.shared.u64 t, %1; cvt.u32.u64 %0, t; }"
        : "=r"(a) : "l"(p));
    return a;
}

// packed f32x2 helpers (dual-lane fp32 FMA on one issue slot)
#define FMA2(d, a, b, c) \
    asm("fma.rn.f32x2 %0, %1, %2, %3;" : "=l"(d) : "l"(a), "l"(b), "l"(c))
#define PACK2(d, lo, hi) \
    asm("mov.b64 %0, {%1, %2};" : "=l"(d) : "f"(lo), "f"(hi))
#define UNPACK2(lo, hi, s) \
    asm("mov.b64 {%0, %1}, %2;" : "=f"(lo), "=f"(hi) : "l"(s))

// ============================================================================
// K1: fused split + mma.sync bf16 projection GEMM (round-11 core).
// z==1 (K) additionally writes the depth-major copy g_Kt.
// ============================================================================
#define PSA 40
#define PSB 72
#define PBUF (128*PSA + 128*PSA + 32*PSB + 32*PSB)
#define PROJ_SMEM (2 * PBUF * 2)

__device__ __forceinline__ void cvt_split4(float4 v, ushort4& h, ushort4& l) {
    float f[4] = {v.x, v.y, v.z, v.w};
    unsigned short* ph = &h.x;
    unsigned short* pl = &l.x;
    #pragma unroll
    for (int i = 0; i < 4; i++) {
        __nv_bfloat16 hi = __float2bfloat16(f[i]);
        ph[i] = __bfloat16_as_ushort(hi);
        pl[i] = __bfloat16_as_ushort(__float2bfloat16(f[i] - __bfloat162float(hi)));
    }
}

__global__ __launch_bounds__(256) void proj_mma_kernel(
    const float* __restrict__ X,
    const float* __restrict__ Wq, const float* __restrict__ bq,
    const float* __restrict__ Wk, const float* __restrict__ bk,
    const float* __restrict__ Wv, const float* __restrict__ bv)
{
    extern __shared__ __align__(16) __nv_bfloat16 smp[];

    const int t = threadIdx.x, warp = t >> 5, lane = t & 31;
    const int wm = warp & 3, wn = warp >> 2;
    const int z = blockIdx.z;
    const int row0 = blockIdx.y * 128, col0 = blockIdx.x * 64;

    if (blockIdx.x == 0 && blockIdx.y == 0 && z == 0 && t < B_*D_*4)
        g_acc[t] = 0.0;

    const float* W   = (z == 0) ? Wq : (z == 1) ? Wk : Wv;
    const float* bias = (z == 0) ? bq : (z == 1) ? bk : bv;
    float* out = (z == 0) ? g_Q : (z == 1) ? g_K : g_V;

    int ar[4], ak[4], br[2], bn[2];
    #pragma unroll
    for (int j = 0; j < 4; j++) { int c = t + j * 256; ar[j] = c >> 3; ak[j] = (c & 7) * 4; }
    #pragma unroll
    for (int j = 0; j < 2; j++) { int c = t + j * 256; br[j] = c >> 4; bn[j] = (c & 15) * 4; }

    float4 raf[4], rbf[2];
    auto ld_regs = [&](int kk) {
        #pragma unroll
        for (int j = 0; j < 4; j++)
            raf[j] = *reinterpret_cast<const float4*>(&X[(size_t)(row0 + ar[j]) * E_ + kk + ak[j]]);
        #pragma unroll
        for (int j = 0; j < 2; j++)
            rbf[j] = *reinterpret_cast<const float4*>(&W[(size_t)(kk + br[j]) * E_ + col0 + bn[j]]);
    };
    auto st_smem = [&](int buf) {
        __nv_bfloat16* Ah = smp + buf * PBUF;
        __nv_bfloat16* Al = Ah + 128 * PSA;
        __nv_bfloat16* Bh = Al + 128 * PSA;
        __nv_bfloat16* Bl = Bh + 32 * PSB;
        #pragma unroll
        for (int j = 0; j < 4; j++) {
            ushort4 h, l;
            cvt_split4(raf[j], h, l);
            *reinterpret_cast<ushort4*>(&Ah[ar[j] * PSA + ak[j]]) = h;
            *reinterpret_cast<ushort4*>(&Al[ar[j] * PSA + ak[j]]) = l;
        }
        #pragma unroll
        for (int j = 0; j < 2; j++) {
            ushort4 h, l;
            cvt_split4(rbf[j], h, l);
            *reinterpret_cast<ushort4*>(&Bh[br[j] * PSB + bn[j]]) = h;
            *reinterpret_cast<ushort4*>(&Bl[br[j] * PSB + bn[j]]) = l;
        }
    };

    float acc[2][4][4];
    #pragma unroll
    for (int mt = 0; mt < 2; mt++)
        #pragma unroll
        for (int nt = 0; nt < 4; nt++)
            #pragma unroll
            for (int i = 0; i < 4; i++) acc[mt][nt][i] = 0.f;

    ld_regs(0);
    st_smem(0);
    __syncthreads();

    int buf = 0;
    for (int it = 0; it < 24; it++) {
        if (it + 1 < 24) ld_regs((it + 1) * 32);

        const __nv_bfloat16* Ah = smp + buf * PBUF;
        const __nv_bfloat16* Al = Ah + 128 * PSA;
        const __nv_bfloat16* Bh = Al + 128 * PSA;
        const __nv_bfloat16* Bl = Bh + 32 * PSB;

        #pragma unroll
        for (int ks = 0; ks < 2; ks++) {
            uint32_t ah[2][4], al[2][4];
            #pragma unroll
            for (int mt = 0; mt < 2; mt++) {
                int arow = wm * 32 + mt * 16 + (lane & 15);
                int acol = ks * 16 + (lane >> 4) * 8;
                uint32_t ad = smem_u32(&Ah[arow * PSA + acol]);
                asm volatile("ldmatrix.sync.aligned.m8n8.x4.shared.b16 {%0,%1,%2,%3}, [%4];"
                    : "=r"(ah[mt][0]), "=r"(ah[mt][1]), "=r"(ah[mt][2]), "=r"(ah[mt][3])
                    : "r"(ad));
                uint32_t ad2 = smem_u32(&Al[arow * PSA + acol]);
                asm volatile("ldmatrix.sync.aligned.m8n8.x4.shared.b16 {%0,%1,%2,%3}, [%4];"
                    : "=r"(al[mt][0]), "=r"(al[mt][1]), "=r"(al[mt][2]), "=r"(al[mt][3])
                    : "r"(ad2));
            }
            #pragma unroll
            for (int nt = 0; nt < 4; nt++) {
                int brow = ks * 16 + (lane & 15);
                int bcol = wn * 32 + nt * 8;
                uint32_t bh0, bh1, bl0, bl1;
                uint32_t bd = smem_u32(&Bh[brow * PSB + bcol]);
                asm volatile("ldmatrix.sync.aligned.m8n8.x2.trans.shared.b16 {%0,%1}, [%2];"
                    : "=r"(bh0), "=r"(bh1) : "r"(bd));
                uint32_t bd2 = smem_u32(&Bl[brow * PSB + bcol]);
                asm volatile("ldmatrix.sync.aligned.m8n8.x2.trans.shared.b16 {%0,%1}, [%2];"
                    : "=r"(bl0), "=r"(bl1) : "r"(bd2));
                #pragma unroll
                for (int mt = 0; mt < 2; mt++) {
                    asm volatile(
                        "mma.sync.aligned.m16n8k16.row.col.f32.bf16.bf16.f32 "
                        "{%0,%1,%2,%3}, {%4,%5,%6,%7}, {%8,%9}, {%0,%1,%2,%3};"
                        : "+f"(acc[mt][nt][0]), "+f"(acc[mt][nt][1]),
                          "+f"(acc[mt][nt][2]), "+f"(acc[mt][nt][3])
                        : "r"(ah[mt][0]), "r"(ah[mt][1]), "r"(ah[mt][2]), "r"(ah[mt][3]),
                          "r"(bh0), "r"(bh1));
                    asm volatile(
                        "mma.sync.aligned.m16n8k16.row.col.f32.bf16.bf16.f32 "
                        "{%0,%1,%2,%3}, {%4,%5,%6,%7}, {%8,%9}, {%0,%1,%2,%3};"
                        : "+f"(acc[mt][nt][0]), "+f"(acc[mt][nt][1]),
                          "+f"(acc[mt][nt][2]), "+f"(acc[mt][nt][3])
                        : "r"(ah[mt][0]), "r"(ah[mt][1]), "r"(ah[mt][2]), "r"(ah[mt][3]),
                          "r"(bl0), "r"(bl1));
                    asm volatile(
                        "mma.sync.aligned.m16n8k16.row.col.f32.bf16.bf16.f32 "
                        "{%0,%1,%2,%3}, {%4,%5,%6,%7}, {%8,%9}, {%0,%1,%2,%3};"
                        : "+f"(acc[mt][nt][0]), "+f"(acc[mt][nt][1]),
                          "+f"(acc[mt][nt][2]), "+f"(acc[mt][nt][3])
                        : "r"(al[mt][0]), "r"(al[mt][1]), "r"(al[mt][2]), "r"(al[mt][3]),
                          "r"(bh0), "r"(bh1));
                }
            }
        }
        __syncthreads();
        if (it + 1 < 24) {
            st_smem(buf ^ 1);
            __syncthreads();
            buf ^= 1;
        }
    }

    #pragma unroll
    for (int mt = 0; mt < 2; mt++) {
        #pragma unroll
        for (int nt = 0; nt < 4; nt++) {
            int r = row0 + wm * 32 + mt * 16 + (lane >> 2);
            int c = col0 + wn * 32 + nt * 8 + (lane & 3) * 2;
            int h = c >> 6, dh = c & 63;
            float bz0 = bias[c], bz1 = bias[c + 1];
            #pragma unroll
            for (int half = 0; half < 2; half++) {
                int rr = r + half * 8;
                int b = rr / L_, l = rr % L_;
                float2 v;
                v.x = acc[mt][nt][half * 2 + 0] + bz0;
                v.y = acc[mt][nt][half * 2 + 1] + bz1;
                *reinterpret_cast<float2*>(
                    &out[(size_t)((b * H_ + h) * L_ + l) * DH_ + dh]) = v;
                if (z == 1) {
                    // depth-major copy: [b,h,d,l,o]
                    int d = dh >> 3, o = dh & 7;
                    *reinterpret_cast<float2*>(
                        &g_Kt[((((size_t)(b * H_ + h)) * D_ + d) * L_ + l) * 8 + o]) = v;
                }
            }
        }
    }
}

// ============================================================================
// K2: branchless stats, m=0; f32x2 dots; 32 q rows/block (round-13 form);
// K slice staged from depth-major g_Kt -> fully coalesced (sector-efficient).
// ============================================================================
__global__ __launch_bounds__(256) void stats_kernel(const float* __restrict__ mask)
{
    __shared__ float sk[L_ * 12];
    __shared__ float sq[32 * 8];
    __shared__ float smask[L_];
    __shared__ float sred[8][4];

    const int t = threadIdx.x;
    const int bhd = blockIdx.x;
    const int d = bhd & 7;
    const int h = (bhd >> 3) % H_;
    const int b = bhd / (8 * H_);
    const int q0 = blockIdx.y * 32;

    const float* Ktb = &g_Kt[(((size_t)(b * H_ + h)) * D_ + d) * L_ * 8];

    // contiguous staging: i -> 16B chunk i of the [768][8] slice
    for (int i = t; i < L_ * 2; i += 256) {
        int k = i >> 1, half = (i & 1) * 4;
        *reinterpret_cast<float4*>(&sk[k * 12 + half]) =
            *reinterpret_cast<const float4*>(&Ktb[i * 4]);
    }
    sq[t] = g_Q[(size_t)((b * H_ + h) * L_ + q0 + (t >> 3)) * DH_ + d * 8 + (t & 7)];
    for (int i = t; i < L_; i += 256) smask[i] = mask[b * L_ + i];
    __syncthreads();

    const int warp = t >> 5, lane = t & 31;
    const int r0 = warp * 4;

    unsigned long long q2[4][4];
    #pragma unroll
    for (int r = 0; r < 4; r++) {
        ulonglong2 qa = *reinterpret_cast<const ulonglong2*>(&sq[(r0 + r) * 8]);
        ulonglong2 qb = *reinterpret_cast<const ulonglong2*>(&sq[(r0 + r) * 8 + 4]);
        q2[r][0] = qa.x; q2[r][1] = qa.y; q2[r][2] = qb.x; q2[r][3] = qb.y;
    }

    const unsigned long long z2 = 0ull;
    float S[4]  = {0.f, 0.f, 0.f, 0.f};
    float E1[4] = {0.f, 0.f, 0.f, 0.f};
    float E2[4] = {0.f, 0.f, 0.f, 0.f};
    float M[4]  = {-1e30f, -1e30f, -1e30f, -1e30f};

    for (int kb = 0; kb < L_; kb += 32) {
        int k = kb + lane;
        ulonglong2 ka = *reinterpret_cast<const ulonglong2*>(&sk[k * 12]);
        ulonglong2 kb2 = *reinterpret_cast<const ulonglong2*>(&sk[k * 12 + 4]);
        unsigned long long k2[4] = {ka.x, ka.y, kb2.x, kb2.y};
        float mk = smask[k];
        #pragma unroll
        for (int r = 0; r < 4; r++) {
            unsigned long long s2;
            FMA2(s2, q2[r][0], k2[0], z2);
            FMA2(s2, q2[r][1], k2[1], s2);
            FMA2(s2, q2[r][2], k2[2], s2);
            FMA2(s2, q2[r][3], k2[3], s2);
            float lo, hi;
            UNPACK2(lo, hi, s2);
            float s = fmaf(lo + hi, INV_SQRT_DS, mk);
            float e = __expf(s);
            S[r]  += e;
            E1[r]  = fmaf(e, s, E1[r]);
            E2[r]  = fmaf(e, e, E2[r]);
            M[r]   = fmaxf(M[r], s);
        }
    }

    #pragma unroll
    for (int r = 0; r < 4; r++) {
        #pragma unroll
        for (int off = 16; off > 0; off >>= 1) {
            S[r]  += __shfl_xor_sync(0xffffffff, S[r],  off);
            E1[r] += __shfl_xor_sync(0xffffffff, E1[r], off);
            E2[r] += __shfl_xor_sync(0xffffffff, E2[r], off);
            M[r]   = fmaxf(M[r], __shfl_xor_sync(0xffffffff, M[r], off));
        }
    }

    if (lane == 0) {
        float psum[4] = {0.f, 0.f, 0.f, 0.f};
        #pragma unroll
        for (int r = 0; r < 4; r++) {
            int row  = q0 + r0 + r;
            int ridx = ((b * H_ + h) * D_ + d) * L_ + row;
            g_S[ridx] = S[r];
            float inv  = 1.0f / S[r];
            float maxp = __expf(M[r]) * inv;
            float hhi  = E2[r] * inv * inv;
            float var  = (hhi - (1.0f / (float)L_)) * (1.0f / (float)(L_ - 1));
            float ent  = __logf(S[r]) - E1[r] * inv;
            psum[0] += var; psum[1] += maxp; psum[2] += hhi; psum[3] += ent;
        }
        #pragma unroll
        for (int i = 0; i < 4; i++) sred[warp][i] = psum[i];
    }
    __syncthreads();
    if (t == 0) {
        double tot[4] = {0, 0, 0, 0};
        #pragma unroll
        for (int w = 0; w < 8; w++)
            #pragma unroll
            for (int i = 0; i < 4; i++) tot[i] += (double)sred[w][i];
        #pragma unroll
        for (int i = 0; i < 4; i++)
            atomicAdd(&g_acc[(b * D_ + d) * 4 + i], tot[i]);
    }
}

// ============================================================================
// K4: attn — weights in prologue; 4q x 4k score tile; m=0; f32x2; float4 sA.
// (round-13 form, unchanged)
// ============================================================================
#define QT 32
#define KT 128
#define KPAD 68
#define APAD 132

__global__ __launch_bounds__(256, 2) void attn_kernel(
    const float* __restrict__ mask,
    float* __restrict__ out_ctx,
    float* __restrict__ out_attn)
{
    extern __shared__ float smem_[];
    float* sQ   = smem_;
    float* sMul = sQ   + QT * DH_;
    float* sW   = sMul + QT * D_;        // 8 gate weights for this b
    float* sK   = sW   + D_;
    float* sV   = sK   + KT * KPAD;
    float* smk  = sV   + KT * KPAD;
    float* sA   = sK;

    const int t    = threadIdx.x;
    const int bh   = blockIdx.x;
    const int b    = bh / H_;
    const int q0   = blockIdx.y * QT;
    const int w    = t >> 5;
    const int lane = t & 31;
    const int kspl = lane >> 3;
    const int dhc  = lane & 7;

    const float* Qbase = &g_Q[(size_t)(bh * L_ + q0) * DH_];
    const float* Kbase = &g_K[(size_t)bh * L_ * DH_];
    const float* Vbase = &g_V[(size_t)bh * L_ * DH_];

    for (int i = t; i < QT * DH_ / 4; i += 256)
        *reinterpret_cast<float4*>(&sQ[i * 4]) =
            *reinterpret_cast<const float4*>(&Qbase[i * 4]);

    // gate weights (stats kernel boundary guarantees g_acc is final)
    if (t < 8) {
        const float scale = 1.0f / (float)(H_ * L_);
        float st[4];
        #pragma unroll
        for (int i = 0; i < 4; i++)
            st[i] = (float)(g_acc[(b * D_ + t) * 4 + i]) * scale;
        float n[4];
        #pragma unroll
        for (int i = 0; i < 4; i++) {
            float vmin = st[i], vmax = st[i];
            #pragma unroll
            for (int off = 1; off < 8; off <<= 1) {
                vmin = fminf(vmin, __shfl_xor_sync(0xff, vmin, off));
                vmax = fmaxf(vmax, __shfl_xor_sync(0xff, vmax, off));
            }
            n[i] = (st[i] - vmin) / fmaxf(vmax - vmin, 1e-12f);
        }
        float score = 0.5f * n[0] + 0.3f * n[1] + 0.2f * n[2] - 0.4f * n[3];
        float smax = score;
        #pragma unroll
        for (int off = 1; off < 8; off <<= 1)
            smax = fmaxf(smax, __shfl_xor_sync(0xff, smax, off));
        float e = __expf(ALPHA_ * (score - smax));
        float ssum = e;
        #pragma unroll
        for (int off = 1; off < 8; off <<= 1)
            ssum += __shfl_xor_sync(0xff, ssum, off);
        sW[t] = e / ssum;
    }
    __syncthreads();
    {
        int q = t >> 3, dd = t & 7;
        int ridx = (bh * D_ + dd) * L_ + q0 + q;
        sMul[q * 8 + dd] = sW[dd] / g_S[ridx];
    }

    const unsigned long long z2 = 0ull;
    unsigned long long ctx2[4][4];
    #pragma unroll
    for (int qi = 0; qi < 4; qi++)
        #pragma unroll
        for (int j = 0; j < 4; j++) ctx2[qi][j] = 0ull;

    for (int kt = 0; kt < L_; kt += KT) {
        __syncthreads();
        for (int i = t; i < KT * DH_ / 4; i += 256) {
            int k = i >> 4, c = (i & 15) * 4;
            *reinterpret_cast<float4*>(&sK[k * KPAD + c]) =
                *reinterpret_cast<const float4*>(&Kbase[(size_t)(kt + k) * DH_ + c]);
            *reinterpret_cast<float4*>(&sV[k * KPAD + c]) =
                *reinterpret_cast<const float4*>(&Vbase[(size_t)(kt + k) * DH_ + c]);
        }
        if (t < KT) smk[t] = mask[b * L_ + kt + t];
        __syncthreads();

        float acc[4][4];
        #pragma unroll
        for (int qi = 0; qi < 4; qi++)
            #pragma unroll
            for (int kj = 0; kj < 4; kj++) acc[qi][kj] = 0.f;

        float mk[4];
        #pragma unroll
        for (int kj = 0; kj < 4; kj++) mk[kj] = smk[lane + 32 * kj];

        #pragma unroll
        for (int dd = 0; dd < D_; dd++) {
            unsigned long long q2[4][4];
            float mu[4];
            #pragma unroll
            for (int qi = 0; qi < 4; qi++) {
                const float* qp = &sQ[(4 * w + qi) * DH_ + dd * 8];
                ulonglong2 qa = *reinterpret_cast<const ulonglong2*>(qp);
                ulonglong2 qb = *reinterpret_cast<const ulonglong2*>(qp + 4);
                q2[qi][0] = qa.x; q2[qi][1] = qa.y;
                q2[qi][2] = qb.x; q2[qi][3] = qb.y;
                mu[qi] = sMul[(4 * w + qi) * 8 + dd];
            }
            #pragma unroll
            for (int kj = 0; kj < 4; kj++) {
                const float* kp = &sK[(lane + 32 * kj) * KPAD + dd * 8];
                ulonglong2 ka = *reinterpret_cast<const ulonglong2*>(kp);
                ulonglong2 kb2 = *reinterpret_cast<const ulonglong2*>(kp + 4);
                unsigned long long k2[4] = {ka.x, ka.y, kb2.x, kb2.y};
                #pragma unroll
                for (int qi = 0; qi < 4; qi++) {
                    unsigned long long s2;
                    FMA2(s2, q2[qi][0], k2[0], z2);
                    FMA2(s2, q2[qi][1], k2[1], s2);
                    FMA2(s2, q2[qi][2], k2[2], s2);
                    FMA2(s2, q2[qi][3], k2[3], s2);
                    float lo, hi;
                    UNPACK2(lo, hi, s2);
                    float s = fmaf(lo + hi, INV_SQRT_DS, mk[kj]);
                    acc[qi][kj] = fmaf(mu[qi], __expf(s), acc[qi][kj]);
                }
            }
        }

        #pragma unroll
        for (int qi = 0; qi < 4; qi++) {
            float* row = &out_attn[(size_t)(bh * L_ + q0 + 4 * w + qi) * L_ + kt];
            #pragma unroll
            for (int kj = 0; kj < 4; kj++)
                row[lane + 32 * kj] = acc[qi][kj];
        }

        __syncthreads();
        #pragma unroll
        for (int qi = 0; qi < 4; qi++)
            #pragma unroll
            for (int kj = 0; kj < 4; kj++)
                sA[(4 * w + qi) * APAD + lane + 32 * kj] = acc[qi][kj];
        __syncthreads();

        // ctx phase: float4 sA loads (groups of 4 consecutive k)
        #pragma unroll
        for (int j = 0; j < 4; j++) {
            const int kbase = 32 * j + 8 * kspl;
            #pragma unroll
            for (int rg = 0; rg < 2; rg++) {
                float4 a4[4];
                #pragma unroll
                for (int qi = 0; qi < 4; qi++)
                    a4[qi] = *reinterpret_cast<const float4*>(
                        &sA[(4 * w + qi) * APAD + kbase + rg * 4]);
                #pragma unroll
                for (int u = 0; u < 4; u++) {
                    int k = kbase + rg * 4 + u;
                    const float* vp = &sV[k * KPAD + dhc * 4];
                    ulonglong2 v01 = *reinterpret_cast<const ulonglong2*>(vp);
                    ulonglong2 v23 = *reinterpret_cast<const ulonglong2*>(vp + 32);
                    #pragma unroll
                    for (int qi = 0; qi < 4; qi++) {
                        float av = (&a4[qi].x)[u];
                        unsigned long long av2;
                        PACK2(av2, av, av);
                        FMA2(ctx2[qi][0], av2, v01.x, ctx2[qi][0]);
                        FMA2(ctx2[qi][1], av2, v01.y, ctx2[qi][1]);
                        FMA2(ctx2[qi][2], av2, v23.x, ctx2[qi][2]);
                        FMA2(ctx2[qi][3], av2, v23.y, ctx2[qi][3]);
                    }
                }
            }
        }
    }

    float ctx[4][8];
    #pragma unroll
    for (int qi = 0; qi < 4; qi++)
        #pragma unroll
        for (int j = 0; j < 4; j++)
            UNPACK2(ctx[qi][j * 2], ctx[qi][j * 2 + 1], ctx2[qi][j]);

    #pragma unroll
    for (int qi = 0; qi < 4; qi++)
        #pragma unroll
        for (int j = 0; j < 8; j++) {
            ctx[qi][j] += __shfl_xor_sync(0xffffffff, ctx[qi][j], 8);
            ctx[qi][j] += __shfl_xor_sync(0xffffffff, ctx[qi][j], 16);
        }

    {
        int qg = q0 + 4 * w + kspl;
        float* op = &out_ctx[(size_t)(b * L_ + qg) * E_ + (bh % H_) * DH_ + dhc * 4];
        *reinterpret_cast<float4*>(op) =
            make_float4(ctx[kspl][0], ctx[kspl][1], ctx[kspl][2], ctx[kspl][3]);
        *reinterpret_cast<float4*>(op + 32) =
            make_float4(ctx[kspl][4], ctx[kspl][5], ctx[kspl][6], ctx[kspl][7]);
    }
}

// ============================================================================
extern "C" void kernel_launch(void* const* d_in, const int* in_sizes, int n_in,
                              void* d_out, int out_size)
{
    const float* hs   = (const float*)d_in[0];
    const float* mask = (const float*)d_in[1];
    const float* Wq   = (const float*)d_in[2];
    const float* bq   = (const float*)d_in[3];
    const float* Wk   = (const float*)d_in[4];
    const float* bk   = (const float*)d_in[5];
    const float* Wv   = (const float*)d_in[6];
    const float* bv   = (const float*)d_in[7];

    float* out_ctx  = (float*)d_out;
    float* out_attn = out_ctx + (size_t)B_ * L_ * E_;

    cudaFuncSetAttribute(proj_mma_kernel,
                         cudaFuncAttributeMaxDynamicSharedMemorySize, PROJ_SMEM);
    proj_mma_kernel<<<dim3(E_ / 64, (B_ * L_) / 128, 3), 256, PROJ_SMEM>>>(
        hs, Wq, bq, Wk, bk, Wv, bv);

    stats_kernel<<<dim3(B_ * H_ * D_, L_ / 32), 256>>>(mask);

    const int smem_bytes = (QT * DH_ + QT * D_ + D_ + 2 * KT * KPAD + KT) * (int)sizeof(float);
    cudaFuncSetAttribute(attn_kernel, cudaFuncAttributeMaxDynamicSharedMemorySize, smem_bytes);
    attn_kernel<<<dim3(B_ * H_, L_ / QT), 256, smem_bytes>>>(mask, out_ctx, out_attn);
}

// round 16
// speedup vs baseline: 1.1693x; 1.0691x over previous
#include <cuda_runtime.h>
#include <cuda_bf16.h>
#include <math.h>
#include <stdint.h>

#define B_  2
#define L_  768
#define E_  768
#define H_  12
#define DH_ 64
#define D_  8
#define DS_ 8
#define INV_SQRT_DS 0.35355339059327373f
#define ALPHA_ 2.5f

// ---------------- scratch (static device globals; no allocation) -------------
__device__ float  g_Q[B_*H_*L_*DH_];
__device__ float  g_K[B_*H_*L_*DH_];
__device__ float  g_V[B_*H_*L_*DH_];
__device__ float  g_S[B_*H_*D_*L_];      // per (b,h,d,q): softmax denom (m=0)
__device__ double g_acc[B_*D_*4];        // sums over (h,q): var, max, hhi, ent

__device__ __forceinline__ uint32_t smem_u32(const void* p) {
    uint32_t a;
    asm("{ .reg .u64 t; cvta.to.shared.u64 t, %1; cvt.u32.u64 %0, t; }"
        : "=r"(a) : "l"(p));
    return a;
}

// packed f32x2 helpers (dual-lane fp32 FMA on one issue slot)
#define FMA2(d, a, b, c) \
    asm("fma.rn.f32x2 %0, %1, %2, %3;" : "=l"(d) : "l"(a), "l"(b), "l"(c))
#define UNPACK2(lo, hi, s) \
    asm("mov.b64 {%0, %1}, %2;" : "=f"(lo), "=f"(hi) : "l"(s))

#define MMA_BF16(accp, a0, a1, a2, a3, b0, b1)                                  \
    asm volatile(                                                               \
        "mma.sync.aligned.m16n8k16.row.col.f32.bf16.bf16.f32 "                  \
        "{%0,%1,%2,%3}, {%4,%5,%6,%7}, {%8,%9}, {%0,%1,%2,%3};"                 \
        : "+f"((accp)[0]), "+f"((accp)[1]), "+f"((accp)[2]), "+f"((accp)[3])    \
        : "r"(a0), "r"(a1), "r"(a2), "r"(a3), "r"(b0), "r"(b1))

// ============================================================================
// K1: fused split + mma.sync bf16 projection GEMM (round-13 form, unchanged).
// ============================================================================
#define PSA 40
#define PSB 72
#define PBUF (128*PSA + 128*PSA + 32*PSB + 32*PSB)
#define PROJ_SMEM (2 * PBUF * 2)

__device__ __forceinline__ void cvt_split4(float4 v, ushort4& h, ushort4& l) {
    float f[4] = {v.x, v.y, v.z, v.w};
    unsigned short* ph = &h.x;
    unsigned short* pl = &l.x;
    #pragma unroll
    for (int i = 0; i < 4; i++) {
        __nv_bfloat16 hi = __float2bfloat16(f[i]);
        ph[i] = __bfloat16_as_ushort(hi);
        pl[i] = __bfloat16_as_ushort(__float2bfloat16(f[i] - __bfloat162float(hi)));
    }
}

__global__ __launch_bounds__(256) void proj_mma_kernel(
    const float* __restrict__ X,
    const float* __restrict__ Wq, const float* __restrict__ bq,
    const float* __restrict__ Wk, const float* __restrict__ bk,
    const float* __restrict__ Wv, const float* __restrict__ bv)
{
    extern __shared__ __align__(16) __nv_bfloat16 smp[];

    const int t = threadIdx.x, warp = t >> 5, lane = t & 31;
    const int wm = warp & 3, wn = warp >> 2;
    const int z = blockIdx.z;
    const int row0 = blockIdx.y * 128, col0 = blockIdx.x * 64;

    if (blockIdx.x == 0 && blockIdx.y == 0 && z == 0 && t < B_*D_*4)
        g_acc[t] = 0.0;

    const float* W   = (z == 0) ? Wq : (z == 1) ? Wk : Wv;
    const float* bias = (z == 0) ? bq : (z == 1) ? bk : bv;
    float* out = (z == 0) ? g_Q : (z == 1) ? g_K : g_V;

    int ar[4], ak[4], br[2], bn[2];
    #pragma unroll
    for (int j = 0; j < 4; j++) { int c = t + j * 256; ar[j] = c >> 3; ak[j] = (c & 7) * 4; }
    #pragma unroll
    for (int j = 0; j < 2; j++) { int c = t + j * 256; br[j] = c >> 4; bn[j] = (c & 15) * 4; }

    float4 raf[4], rbf[2];
    auto ld_regs = [&](int kk) {
        #pragma unroll
        for (int j = 0; j < 4; j++)
            raf[j] = *reinterpret_cast<const float4*>(&X[(size_t)(row0 + ar[j]) * E_ + kk + ak[j]]);
        #pragma unroll
        for (int j = 0; j < 2; j++)
            rbf[j] = *reinterpret_cast<const float4*>(&W[(size_t)(kk + br[j]) * E_ + col0 + bn[j]]);
    };
    auto st_smem = [&](int buf) {
        __nv_bfloat16* Ah = smp + buf * PBUF;
        __nv_bfloat16* Al = Ah + 128 * PSA;
        __nv_bfloat16* Bh = Al + 128 * PSA;
        __nv_bfloat16* Bl = Bh + 32 * PSB;
        #pragma unroll
        for (int j = 0; j < 4; j++) {
            ushort4 h, l;
            cvt_split4(raf[j], h, l);
            *reinterpret_cast<ushort4*>(&Ah[ar[j] * PSA + ak[j]]) = h;
            *reinterpret_cast<ushort4*>(&Al[ar[j] * PSA + ak[j]]) = l;
        }
        #pragma unroll
        for (int j = 0; j < 2; j++) {
            ushort4 h, l;
            cvt_split4(rbf[j], h, l);
            *reinterpret_cast<ushort4*>(&Bh[br[j] * PSB + bn[j]]) = h;
            *reinterpret_cast<ushort4*>(&Bl[br[j] * PSB + bn[j]]) = l;
        }
    };

    float acc[2][4][4];
    #pragma unroll
    for (int mt = 0; mt < 2; mt++)
        #pragma unroll
        for (int nt = 0; nt < 4; nt++)
            #pragma unroll
            for (int i = 0; i < 4; i++) acc[mt][nt][i] = 0.f;

    ld_regs(0);
    st_smem(0);
    __syncthreads();

    int buf = 0;
    for (int it = 0; it < 24; it++) {
        if (it + 1 < 24) ld_regs((it + 1) * 32);

        const __nv_bfloat16* Ah = smp + buf * PBUF;
        const __nv_bfloat16* Al = Ah + 128 * PSA;
        const __nv_bfloat16* Bh = Al + 128 * PSA;
        const __nv_bfloat16* Bl = Bh + 32 * PSB;

        #pragma unroll
        for (int ks = 0; ks < 2; ks++) {
            uint32_t ah[2][4], al[2][4];
            #pragma unroll
            for (int mt = 0; mt < 2; mt++) {
                int arow = wm * 32 + mt * 16 + (lane & 15);
                int acol = ks * 16 + (lane >> 4) * 8;
                uint32_t ad = smem_u32(&Ah[arow * PSA + acol]);
                asm volatile("ldmatrix.sync.aligned.m8n8.x4.shared.b16 {%0,%1,%2,%3}, [%4];"
                    : "=r"(ah[mt][0]), "=r"(ah[mt][1]), "=r"(ah[mt][2]), "=r"(ah[mt][3])
                    : "r"(ad));
                uint32_t ad2 = smem_u32(&Al[arow * PSA + acol]);
                asm volatile("ldmatrix.sync.aligned.m8n8.x4.shared.b16 {%0,%1,%2,%3}, [%4];"
                    : "=r"(al[mt][0]), "=r"(al[mt][1]), "=r"(al[mt][2]), "=r"(al[mt][3])
                    : "r"(ad2));
            }
            #pragma unroll
            for (int nt = 0; nt < 4; nt++) {
                int brow = ks * 16 + (lane & 15);
                int bcol = wn * 32 + nt * 8;
                uint32_t bh0, bh1, bl0, bl1;
                uint32_t bd = smem_u32(&Bh[brow * PSB + bcol]);
                asm volatile("ldmatrix.sync.aligned.m8n8.x2.trans.shared.b16 {%0,%1}, [%2];"
                    : "=r"(bh0), "=r"(bh1) : "r"(bd));
                uint32_t bd2 = smem_u32(&Bl[brow * PSB + bcol]);
                asm volatile("ldmatrix.sync.aligned.m8n8.x2.trans.shared.b16 {%0,%1}, [%2];"
                    : "=r"(bl0), "=r"(bl1) : "r"(bd2));
                #pragma unroll
                for (int mt = 0; mt < 2; mt++) {
                    MMA_BF16(acc[mt][nt], ah[mt][0], ah[mt][1], ah[mt][2], ah[mt][3], bh0, bh1);
                    MMA_BF16(acc[mt][nt], ah[mt][0], ah[mt][1], ah[mt][2], ah[mt][3], bl0, bl1);
                    MMA_BF16(acc[mt][nt], al[mt][0], al[mt][1], al[mt][2], al[mt][3], bh0, bh1);
                }
            }
        }
        __syncthreads();
        if (it + 1 < 24) {
            st_smem(buf ^ 1);
            __syncthreads();
            buf ^= 1;
        }
    }

    #pragma unroll
    for (int mt = 0; mt < 2; mt++) {
        #pragma unroll
        for (int nt = 0; nt < 4; nt++) {
            int r = row0 + wm * 32 + mt * 16 + (lane >> 2);
            int c = col0 + wn * 32 + nt * 8 + (lane & 3) * 2;
            int h = c >> 6, dh = c & 63;
            float bz0 = bias[c], bz1 = bias[c + 1];
            #pragma unroll
            for (int half = 0; half < 2; half++) {
                int rr = r + half * 8;
                int b = rr / L_, l = rr % L_;
                float2 v;
                v.x = acc[mt][nt][half * 2 + 0] + bz0;
                v.y = acc[mt][nt][half * 2 + 1] + bz1;
                *reinterpret_cast<float2*>(
                    &out[(size_t)((b * H_ + h) * L_ + l) * DH_ + dh]) = v;
            }
        }
    }
}

// ============================================================================
// K2: branchless stats, m=0; f32x2 dots; 32 q rows/block (round-13 form).
// ============================================================================
__global__ __launch_bounds__(256) void stats_kernel(const float* __restrict__ mask)
{
    __shared__ float sk[L_ * 12];
    __shared__ float sq[32 * 8];
    __shared__ float smask[L_];
    __shared__ float sred[8][4];

    const int t = threadIdx.x;
    const int bhd = blockIdx.x;
    const int d = bhd & 7;
    const int h = (bhd >> 3) % H_;
    const int b = bhd / (8 * H_);
    const int q0 = blockIdx.y * 32;

    const float* Kbase = &g_K[(size_t)(b * H_ + h) * L_ * DH_ + d * 8];

    for (int i = t; i < L_ * 2; i += 256) {
        int k = i >> 1, half = (i & 1) * 4;
        *reinterpret_cast<float4*>(&sk[k * 12 + half]) =
            *reinterpret_cast<const float4*>(&Kbase[(size_t)k * DH_ + half]);
    }
    sq[t] = g_Q[(size_t)((b * H_ + h) * L_ + q0 + (t >> 3)) * DH_ + d * 8 + (t & 7)];
    for (int i = t; i < L_; i += 256) smask[i] = mask[b * L_ + i];
    __syncthreads();

    const int warp = t >> 5, lane = t & 31;
    const int r0 = warp * 4;

    unsigned long long q2[4][4];
    #pragma unroll
    for (int r = 0; r < 4; r++) {
        ulonglong2 qa = *reinterpret_cast<const ulonglong2*>(&sq[(r0 + r) * 8]);
        ulonglong2 qb = *reinterpret_cast<const ulonglong2*>(&sq[(r0 + r) * 8 + 4]);
        q2[r][0] = qa.x; q2[r][1] = qa.y; q2[r][2] = qb.x; q2[r][3] = qb.y;
    }

    const unsigned long long z2 = 0ull;
    float S[4]  = {0.f, 0.f, 0.f, 0.f};
    float E1[4] = {0.f, 0.f, 0.f, 0.f};
    float E2[4] = {0.f, 0.f, 0.f, 0.f};
    float M[4]  = {-1e30f, -1e30f, -1e30f, -1e30f};

    for (int kb = 0; kb < L_; kb += 32) {
        int k = kb + lane;
        ulonglong2 ka = *reinterpret_cast<const ulonglong2*>(&sk[k * 12]);
        ulonglong2 kb2 = *reinterpret_cast<const ulonglong2*>(&sk[k * 12 + 4]);
        unsigned long long k2[4] = {ka.x, ka.y, kb2.x, kb2.y};
        float mk = smask[k];
        #pragma unroll
        for (int r = 0; r < 4; r++) {
            unsigned long long s2;
            FMA2(s2, q2[r][0], k2[0], z2);
            FMA2(s2, q2[r][1], k2[1], s2);
            FMA2(s2, q2[r][2], k2[2], s2);
            FMA2(s2, q2[r][3], k2[3], s2);
            float lo, hi;
            UNPACK2(lo, hi, s2);
            float s = fmaf(lo + hi, INV_SQRT_DS, mk);
            float e = __expf(s);
            S[r]  += e;
            E1[r]  = fmaf(e, s, E1[r]);
            E2[r]  = fmaf(e, e, E2[r]);
            M[r]   = fmaxf(M[r], s);
        }
    }

    #pragma unroll
    for (int r = 0; r < 4; r++) {
        #pragma unroll
        for (int off = 16; off > 0; off >>= 1) {
            S[r]  += __shfl_xor_sync(0xffffffff, S[r],  off);
            E1[r] += __shfl_xor_sync(0xffffffff, E1[r], off);
            E2[r] += __shfl_xor_sync(0xffffffff, E2[r], off);
            M[r]   = fmaxf(M[r], __shfl_xor_sync(0xffffffff, M[r], off));
        }
    }

    if (lane == 0) {
        float psum[4] = {0.f, 0.f, 0.f, 0.f};
        #pragma unroll
        for (int r = 0; r < 4; r++) {
            int row  = q0 + r0 + r;
            int ridx = ((b * H_ + h) * D_ + d) * L_ + row;
            g_S[ridx] = S[r];
            float inv  = 1.0f / S[r];
            float maxp = __expf(M[r]) * inv;
            float hhi  = E2[r] * inv * inv;
            float var  = (hhi - (1.0f / (float)L_)) * (1.0f / (float)(L_ - 1));
            float ent  = __logf(S[r]) - E1[r] * inv;
            psum[0] += var; psum[1] += maxp; psum[2] += hhi; psum[3] += ent;
        }
        #pragma unroll
        for (int i = 0; i < 4; i++) sred[warp][i] = psum[i];
    }
    __syncthreads();
    if (t == 0) {
        double tot[4] = {0, 0, 0, 0};
        #pragma unroll
        for (int w = 0; w < 8; w++)
            #pragma unroll
            for (int i = 0; i < 4; i++) tot[i] += (double)sred[w][i];
        #pragma unroll
        for (int i = 0; i < 4; i++)
            atomicAdd(&g_acc[(b * D_ + d) * 4 + i], tot[i]);
    }
}

// ============================================================================
// K4 (v5): attn — score phase f32x2 (unchanged), ctx phase on TENSOR CORES:
// attn values split to bf16 hi/lo in smem, V staged bf16 hi/lo, per-warp
// 16q x 16dh output tile accumulated over K=768 via m16n8k16 (3-product).
// ============================================================================
#define QT 32
#define KT 128
#define KPAD 68
#define SAB 136   // attn bf16 row stride (272B = 17x16B, ldmatrix conflict-free)
#define SVB 72    // V bf16 row stride (144B = 9x16B)

// float region: sQ 2048 + sMul 256 + sW 8 + smk 128 + sK 8704 = 11144 floats
#define ATTN_F32_WORDS (QT*DH_ + QT*D_ + D_ + KT + KT*KPAD)
#define ATTN_BF16_OFF  (ATTN_F32_WORDS * 4)
#define ATTN_SMEM (ATTN_BF16_OFF + (2 * KT * SVB + 2 * QT * SAB) * 2)

__global__ __launch_bounds__(256, 2) void attn_kernel(
    const float* __restrict__ mask,
    float* __restrict__ out_ctx,
    float* __restrict__ out_attn)
{
    extern __shared__ __align__(16) char smc[];
    float* sQ   = reinterpret_cast<float*>(smc);
    float* sMul = sQ   + QT * DH_;
    float* sW   = sMul + QT * D_;
    float* smk  = sW   + D_;
    float* sK   = smk  + KT;
    __nv_bfloat16* sVh = reinterpret_cast<__nv_bfloat16*>(smc + ATTN_BF16_OFF);
    __nv_bfloat16* sVl = sVh + KT * SVB;
    __nv_bfloat16* sAh = sVl + KT * SVB;
    __nv_bfloat16* sAl = sAh + QT * SAB;

    const int t    = threadIdx.x;
    const int bh   = blockIdx.x;
    const int b    = bh / H_;
    const int q0   = blockIdx.y * QT;
    const int w    = t >> 5;
    const int lane = t & 31;
    const int mi   = w & 1;        // ctx warp tile: m half
    const int ni   = w >> 1;       // ctx warp tile: n quarter (16 dh)

    const float* Qbase = &g_Q[(size_t)(bh * L_ + q0) * DH_];
    const float* Kbase = &g_K[(size_t)bh * L_ * DH_];
    const float* Vbase = &g_V[(size_t)bh * L_ * DH_];

    for (int i = t; i < QT * DH_ / 4; i += 256)
        *reinterpret_cast<float4*>(&sQ[i * 4]) =
            *reinterpret_cast<const float4*>(&Qbase[i * 4]);

    // gate weights (stats kernel boundary guarantees g_acc is final)
    if (t < 8) {
        const float scale = 1.0f / (float)(H_ * L_);
        float st[4];
        #pragma unroll
        for (int i = 0; i < 4; i++)
            st[i] = (float)(g_acc[(b * D_ + t) * 4 + i]) * scale;
        float n[4];
        #pragma unroll
        for (int i = 0; i < 4; i++) {
            float vmin = st[i], vmax = st[i];
            #pragma unroll
            for (int off = 1; off < 8; off <<= 1) {
                vmin = fminf(vmin, __shfl_xor_sync(0xff, vmin, off));
                vmax = fmaxf(vmax, __shfl_xor_sync(0xff, vmax, off));
            }
            n[i] = (st[i] - vmin) / fmaxf(vmax - vmin, 1e-12f);
        }
        float score = 0.5f * n[0] + 0.3f * n[1] + 0.2f * n[2] - 0.4f * n[3];
        float smax = score;
        #pragma unroll
        for (int off = 1; off < 8; off <<= 1)
            smax = fmaxf(smax, __shfl_xor_sync(0xff, smax, off));
        float e = __expf(ALPHA_ * (score - smax));
        float ssum = e;
        #pragma unroll
        for (int off = 1; off < 8; off <<= 1)
            ssum += __shfl_xor_sync(0xff, ssum, off);
        sW[t] = e / ssum;
    }
    __syncthreads();
    {
        int q = t >> 3, dd = t & 7;
        int ridx = (bh * D_ + dd) * L_ + q0 + q;
        sMul[q * 8 + dd] = sW[dd] / g_S[ridx];
    }

    const unsigned long long z2 = 0ull;
    float cacc[2][4];
    #pragma unroll
    for (int nt = 0; nt < 2; nt++)
        #pragma unroll
        for (int i = 0; i < 4; i++) cacc[nt][i] = 0.f;

    for (int kt = 0; kt < L_; kt += KT) {
        __syncthreads();
        // stage K (fp32) and V (bf16 hi/lo)
        for (int i = t; i < KT * DH_ / 4; i += 256) {
            int k = i >> 4, c = (i & 15) * 4;
            *reinterpret_cast<float4*>(&sK[k * KPAD + c]) =
                *reinterpret_cast<const float4*>(&Kbase[(size_t)(kt + k) * DH_ + c]);
            float4 vv = *reinterpret_cast<const float4*>(&Vbase[(size_t)(kt + k) * DH_ + c]);
            ushort4 vh, vl;
            cvt_split4(vv, vh, vl);
            *reinterpret_cast<ushort4*>(&sVh[k * SVB + c]) = vh;
            *reinterpret_cast<ushort4*>(&sVl[k * SVB + c]) = vl;
        }
        if (t < KT) smk[t] = mask[b * L_ + kt + t];
        __syncthreads();

        // ---------------- score phase (f32x2) ----------------
        float acc[4][4];
        #pragma unroll
        for (int qi = 0; qi < 4; qi++)
            #pragma unroll
            for (int kj = 0; kj < 4; kj++) acc[qi][kj] = 0.f;

        float mk[4];
        #pragma unroll
        for (int kj = 0; kj < 4; kj++) mk[kj] = smk[lane + 32 * kj];

        #pragma unroll
        for (int dd = 0; dd < D_; dd++) {
            unsigned long long q2[4][4];
            float mu[4];
            #pragma unroll
            for (int qi = 0; qi < 4; qi++) {
                const float* qp = &sQ[(4 * w + qi) * DH_ + dd * 8];
                ulonglong2 qa = *reinterpret_cast<const ulonglong2*>(qp);
                ulonglong2 qb = *reinterpret_cast<const ulonglong2*>(qp + 4);
                q2[qi][0] = qa.x; q2[qi][1] = qa.y;
                q2[qi][2] = qb.x; q2[qi][3] = qb.y;
                mu[qi] = sMul[(4 * w + qi) * 8 + dd];
            }
            #pragma unroll
            for (int kj = 0; kj < 4; kj++) {
                const float* kp = &sK[(lane + 32 * kj) * KPAD + dd * 8];
                ulonglong2 ka = *reinterpret_cast<const ulonglong2*>(kp);
                ulonglong2 kb2 = *reinterpret_cast<const ulonglong2*>(kp + 4);
                unsigned long long k2[4] = {ka.x, ka.y, kb2.x, kb2.y};
                #pragma unroll
                for (int qi = 0; qi < 4; qi++) {
                    unsigned long long s2;
                    FMA2(s2, q2[qi][0], k2[0], z2);
                    FMA2(s2, q2[qi][1], k2[1], s2);
                    FMA2(s2, q2[qi][2], k2[2], s2);
                    FMA2(s2, q2[qi][3], k2[3], s2);
                    float lo, hi;
                    UNPACK2(lo, hi, s2);
                    float s = fmaf(lo + hi, INV_SQRT_DS, mk[kj]);
                    acc[qi][kj] = fmaf(mu[qi], __expf(s), acc[qi][kj]);
                }
            }
        }

        // attn4 write (fp32, from registers, coalesced)
        #pragma unroll
        for (int qi = 0; qi < 4; qi++) {
            float* row = &out_attn[(size_t)(bh * L_ + q0 + 4 * w + qi) * L_ + kt];
            #pragma unroll
            for (int kj = 0; kj < 4; kj++)
                row[lane + 32 * kj] = acc[qi][kj];
        }

        // stage attn values as bf16 hi/lo for the ctx MMA
        #pragma unroll
        for (int qi = 0; qi < 4; qi++)
            #pragma unroll
            for (int kj = 0; kj < 4; kj++) {
                float v = acc[qi][kj];
                __nv_bfloat16 hi = __float2bfloat16(v);
                __nv_bfloat16 lo = __float2bfloat16(v - __bfloat162float(hi));
                int idx = (4 * w + qi) * SAB + lane + 32 * kj;
                sAh[idx] = hi;
                sAl[idx] = lo;
            }
        __syncthreads();

        // ---------------- ctx phase: tensor cores ----------------
        #pragma unroll
        for (int ks = 0; ks < 8; ks++) {
            uint32_t ah[4], al[4];
            int arow = mi * 16 + (lane & 15);
            int acol = ks * 16 + (lane >> 4) * 8;
            uint32_t ad = smem_u32(&sAh[arow * SAB + acol]);
            asm volatile("ldmatrix.sync.aligned.m8n8.x4.shared.b16 {%0,%1,%2,%3}, [%4];"
                : "=r"(ah[0]), "=r"(ah[1]), "=r"(ah[2]), "=r"(ah[3]) : "r"(ad));
            uint32_t ad2 = smem_u32(&sAl[arow * SAB + acol]);
            asm volatile("ldmatrix.sync.aligned.m8n8.x4.shared.b16 {%0,%1,%2,%3}, [%4];"
                : "=r"(al[0]), "=r"(al[1]), "=r"(al[2]), "=r"(al[3]) : "r"(ad2));
            #pragma unroll
            for (int nt = 0; nt < 2; nt++) {
                int brow = ks * 16 + (lane & 15);
                int bcol = ni * 16 + nt * 8;
                uint32_t bh0, bh1, bl0, bl1;
                uint32_t bd = smem_u32(&sVh[brow * SVB + bcol]);
                asm volatile("ldmatrix.sync.aligned.m8n8.x2.trans.shared.b16 {%0,%1}, [%2];"
                    : "=r"(bh0), "=r"(bh1) : "r"(bd));
                uint32_t bd2 = smem_u32(&sVl[brow * SVB + bcol]);
                asm volatile("ldmatrix.sync.aligned.m8n8.x2.trans.shared.b16 {%0,%1}, [%2];"
                    : "=r"(bl0), "=r"(bl1) : "r"(bd2));
                MMA_BF16(cacc[nt], ah[0], ah[1], ah[2], ah[3], bh0, bh1);
                MMA_BF16(cacc[nt], ah[0], ah[1], ah[2], ah[3], bl0, bl1);
                MMA_BF16(cacc[nt], al[0], al[1], al[2], al[3], bh0, bh1);
            }
        }
    }

    // epilogue: mma acc layout -> out_ctx
    {
        const int hh = bh % H_;
        #pragma unroll
        for (int nt = 0; nt < 2; nt++) {
            int r = q0 + mi * 16 + (lane >> 2);
            int c = hh * DH_ + ni * 16 + nt * 8 + (lane & 3) * 2;
            float2 v0 = make_float2(cacc[nt][0], cacc[nt][1]);
            float2 v1 = make_float2(cacc[nt][2], cacc[nt][3]);
            *reinterpret_cast<float2*>(&out_ctx[(size_t)(b * L_ + r) * E_ + c]) = v0;
            *reinterpret_cast<float2*>(&out_ctx[(size_t)(b * L_ + r + 8) * E_ + c]) = v1;
        }
    }
}

// ============================================================================
extern "C" void kernel_launch(void* const* d_in, const int* in_sizes, int n_in,
                              void* d_out, int out_size)
{
    const float* hs   = (const float*)d_in[0];
    const float* mask = (const float*)d_in[1];
    const float* Wq   = (const float*)d_in[2];
    const float* bq   = (const float*)d_in[3];
    const float* Wk   = (const float*)d_in[4];
    const float* bk   = (const float*)d_in[5];
    const float* Wv   = (const float*)d_in[6];
    const float* bv   = (const float*)d_in[7];

    float* out_ctx  = (float*)d_out;
    float* out_attn = out_ctx + (size_t)B_ * L_ * E_;

    cudaFuncSetAttribute(proj_mma_kernel,
                         cudaFuncAttributeMaxDynamicSharedMemorySize, PROJ_SMEM);
    proj_mma_kernel<<<dim3(E_ / 64, (B_ * L_) / 128, 3), 256, PROJ_SMEM>>>(
        hs, Wq, bq, Wk, bk, Wv, bv);

    stats_kernel<<<dim3(B_ * H_ * D_, L_ / 32), 256>>>(mask);

    cudaFuncSetAttribute(attn_kernel,
                         cudaFuncAttributeMaxDynamicSharedMemorySize, ATTN_SMEM);
    attn_kernel<<<dim3(B_ * H_, L_ / QT), 256, ATTN_SMEM>>>(mask, out_ctx, out_attn);
}